// round 1
// baseline (speedup 1.0000x reference)
#include <cuda_runtime.h>
#include <cuda_bf16.h>

#define Bz   16
#define Tz   512
#define Dz   384
#define Kz   3
#define ROWS (Bz*Tz)     // 8192
#define TILE 16          // rows per conv block (512 % 16 == 0, tiles never cross batch)

// ---------------- scratch (device globals; no allocation allowed) ----------------
__device__ float g_wt1[Dz*Kz*Dz];   // w1 transposed to [O][K][I]
__device__ float g_wt2[Dz*Kz*Dz];   // w2 transposed
__device__ float g_h1[ROWS*Dz];     // hidden after layer 1
__device__ float g_h2[ROWS*Dz];     // hidden after layer 2
__device__ int   g_cum[ROWS];       // per-batch inclusive cumsum of durations

// ---------------- weight transpose: w[O][I][K] -> wt[O][K][I] ----------------
__global__ void transpose_w_kernel(const float* __restrict__ w, int stage) {
    float* wt = (stage == 0) ? g_wt1 : g_wt2;
    int idx = blockIdx.x * blockDim.x + threadIdx.x;
    if (idx >= Dz*Dz*Kz) return;
    int k = idx % Kz;
    int i = (idx / Kz) % Dz;
    int o = idx / (Kz*Dz);
    wt[(o*Kz + k)*Dz + i] = w[idx];
}

// ---------------- fused conv1d(K=3,'same') + LayerNorm + ReLU ----------------
// stage 0: in = x (param), wt = g_wt1, out = g_h1
// stage 1: in = g_h1,      wt = g_wt2, out = g_h2
__global__ void __launch_bounds__(Dz) conv_ln_relu_kernel(
    const float* __restrict__ x_in,
    const float* __restrict__ bias,
    const float* __restrict__ gamma,
    const float* __restrict__ beta,
    int stage)
{
    __shared__ float patch[(TILE+2)*Dz];   // input rows t0-1 .. t0+TILE  (27648 B)
    __shared__ float s_mean[TILE];
    __shared__ float s_rstd[TILE];

    const float* in  = (stage == 0) ? x_in : g_h1;
    const float* wt  = (stage == 0) ? g_wt1 : g_wt2;
    float*       out = (stage == 0) ? g_h1 : g_h2;

    const int o = threadIdx.x;                 // output channel
    const int tilesPerB = Tz / TILE;           // 32
    const int b  = blockIdx.x / tilesPerB;
    const int t0 = (blockIdx.x % tilesPerB) * TILE;
    const float* inB = in + (size_t)b * Tz * Dz;

    // load input patch (zero padding at sequence boundaries)
    #pragma unroll
    for (int pr = 0; pr < TILE + 2; pr++) {
        int t = t0 + pr - 1;
        patch[pr*Dz + o] = (t >= 0 && t < Tz) ? inB[(size_t)t*Dz + o] : 0.f;
    }
    __syncthreads();

    float acc[TILE];
    {
        float bv = bias[o];
        #pragma unroll
        for (int r = 0; r < TILE; r++) acc[r] = bv;
    }

    // GEMM core: acc[r] += sum_k sum_i patch[r+k][i] * wt[o][k][i]
    const float4* wt4 = (const float4*)(wt + (size_t)o * Kz * Dz);
    const float4* p4  = (const float4*)patch;
    #pragma unroll
    for (int k = 0; k < Kz; k++) {
        #pragma unroll 4
        for (int i4 = 0; i4 < Dz/4; i4++) {
            float4 w = wt4[k*(Dz/4) + i4];
            #pragma unroll
            for (int r = 0; r < TILE; r++) {
                float4 xv = p4[(r + k)*(Dz/4) + i4];   // uniform -> smem broadcast
                acc[r] += w.x*xv.x + w.y*xv.y + w.z*xv.z + w.w*xv.w;
            }
        }
    }

    // stash conv outputs in smem (reuse patch) for LN reductions
    __syncthreads();
    #pragma unroll
    for (int r = 0; r < TILE; r++) patch[r*Dz + o] = acc[r];
    __syncthreads();

    // per-row mean / rstd (warp per row; 12 warps cover 16 rows in <=2 passes)
    const int warp = o >> 5, lane = o & 31;
    for (int r = warp; r < TILE; r += 12) {
        float s = 0.f, sq = 0.f;
        #pragma unroll
        for (int i = lane; i < Dz; i += 32) {
            float v = patch[r*Dz + i];
            s += v; sq += v*v;
        }
        #pragma unroll
        for (int off = 16; off > 0; off >>= 1) {
            s  += __shfl_xor_sync(0xffffffffu, s,  off);
            sq += __shfl_xor_sync(0xffffffffu, sq, off);
        }
        if (lane == 0) {
            float m = s * (1.f/Dz);
            float var = sq * (1.f/Dz) - m*m;
            s_mean[r] = m;
            s_rstd[r] = rsqrtf(var + 1e-5f);
        }
    }
    __syncthreads();

    const float go = gamma[o], bo = beta[o];
    float* outB = out + ((size_t)b*Tz + t0) * Dz;
    #pragma unroll
    for (int r = 0; r < TILE; r++) {
        float v = (patch[r*Dz + o] - s_mean[r]) * s_rstd[r] * go + bo;
        outB[(size_t)r*Dz + o] = fmaxf(v, 0.f);
    }
}

// ---------------- pred = h2 @ wl + bl  (warp per row) ----------------
__global__ void pred_kernel(const float* __restrict__ wl,
                            const float* __restrict__ bl,
                            float* __restrict__ pred)
{
    int row  = blockIdx.x * (blockDim.x >> 5) + (threadIdx.x >> 5);
    int lane = threadIdx.x & 31;
    if (row >= ROWS) return;
    const float* hr = g_h2 + (size_t)row * Dz;
    float s = 0.f;
    #pragma unroll
    for (int i = lane; i < Dz; i += 32) s += hr[i] * wl[i];
    #pragma unroll
    for (int off = 16; off > 0; off >>= 1) s += __shfl_xor_sync(0xffffffffu, s, off);
    if (lane == 0) pred[row] = s + bl[0];
}

// ---------------- per-batch inclusive cumsum of durations ----------------
__global__ void scan_kernel(const int* __restrict__ dur) {
    __shared__ int s[Tz];
    int b = blockIdx.x, t = threadIdx.x;
    s[t] = dur[b*Tz + t];
    __syncthreads();
    for (int off = 1; off < Tz; off <<= 1) {
        int v = (t >= off) ? s[t - off] : 0;
        __syncthreads();
        s[t] += v;
        __syncthreads();
    }
    g_cum[b*Tz + t] = s[t];
}

// ---------------- expansion: expanded[b,l,:] = x[b,j,:] with cum[j-1]<=l<cum[j] ----------------
__global__ void expand_kernel(const float* __restrict__ x,
                              float* __restrict__ out, int L)
{
    int l = blockIdx.x, b = blockIdx.y;
    const int* cb = g_cum + b*Tz;
    int total = cb[Tz - 1];
    float4* o4 = (float4*)(out + ((size_t)b*L + l) * Dz);
    int tid = threadIdx.x;                 // 96 threads, float4 each -> 384 floats
    if (l >= total) {
        o4[tid] = make_float4(0.f, 0.f, 0.f, 0.f);
        return;
    }
    int lo = 0, hi = Tz - 1;
    while (lo < hi) {                      // first j with cum[j] > l
        int mid = (lo + hi) >> 1;
        if (cb[mid] > l) hi = mid; else lo = mid + 1;
    }
    const float4* x4 = (const float4*)(x + ((size_t)b*Tz + lo) * Dz);
    o4[tid] = x4[tid];
}

// ---------------- launch ----------------
extern "C" void kernel_launch(void* const* d_in, const int* in_sizes, int n_in,
                              void* d_out, int out_size)
{
    const float* x   = (const float*)d_in[0];
    const int*   dur = (const int*)  d_in[1];
    const float* w1  = (const float*)d_in[2];
    const float* b1  = (const float*)d_in[3];
    const float* g1  = (const float*)d_in[4];
    const float* be1 = (const float*)d_in[5];
    const float* w2  = (const float*)d_in[6];
    const float* b2  = (const float*)d_in[7];
    const float* g2  = (const float*)d_in[8];
    const float* be2 = (const float*)d_in[9];
    const float* wl  = (const float*)d_in[10];
    const float* bl  = (const float*)d_in[11];
    float* out = (float*)d_out;

    // out = [expanded B*L*D | pred B*T]
    int L = (out_size - Bz*Tz) / (Bz*Dz);
    float* pred_out = out + (size_t)Bz * L * Dz;

    const int WN = Dz*Dz*Kz;
    transpose_w_kernel<<<(WN + 255)/256, 256>>>(w1, 0);
    transpose_w_kernel<<<(WN + 255)/256, 256>>>(w2, 1);

    conv_ln_relu_kernel<<<ROWS/TILE, Dz>>>(x, b1, g1, be1, 0);
    conv_ln_relu_kernel<<<ROWS/TILE, Dz>>>(x, b2, g2, be2, 1);

    pred_kernel<<<(ROWS + 7)/8, 256>>>(wl, bl, pred_out);

    scan_kernel<<<Bz, Tz>>>(dur);
    expand_kernel<<<dim3(L, Bz), 96>>>(x, out, L);
}